// round 14
// baseline (speedup 1.0000x reference)
#include <cuda_runtime.h>
#include <cuda_fp16.h>
#include <math.h>
#include <stdint.h>

#define N_NODES 50000
#define N_EDGES 800000
#define NF 128
#define NH 512
#define NBLK 196               // ceil(50000/256)
#define NE2_BLOCKS 1563        // ceil((800000/2)/256)
#define W1T_BLOCKS 256         // 65536/256
#define XS_BLOCKS 6250         // (50000*128/4)/256

// ---------------- scratch (device globals; zero-initialized at load) ------
__device__ float g_dinv[N_NODES];
__device__ int   g_cnt[N_NODES];       // ALWAYS zero at kernel_launch entry
__device__ int   g_rowptr[N_NODES + 1];
__device__ int   g_cursor[N_NODES];
__device__ int   g_col[N_EDGES];
__device__ __align__(16) __half g_Xs_h[(size_t)N_NODES * NF];   // dinv*X fp16
__device__ __align__(16) __half g_AX_h[(size_t)N_NODES * NF];
__device__ __align__(16) __half g_W1T_h[(size_t)NH * NF];
__device__ float2 g_HW2[N_NODES];

__device__ __forceinline__ uint32_t smem_u32(const void* p) {
    uint32_t a;
    asm("{ .reg .u64 t; cvta.to.shared.u64 t, %1; cvt.u32.u64 %0, t; }" : "=r"(a) : "l"(p));
    return a;
}
__device__ __forceinline__ void cp16(uint32_t dst, const void* src, int sz) {
    asm volatile("cp.async.cg.shared.global [%0], [%1], 16, %2;"
                 :: "r"(dst), "l"(src), "r"(sz));
}
#define CP_COMMIT() asm volatile("cp.async.commit_group;" ::: "memory")
#define CP_WAIT0()  asm volatile("cp.async.wait_group 0;" ::: "memory")

__device__ __forceinline__ int clampi(int v) {
    v = v < 0 ? 0 : v;
    return v >= N_NODES ? N_NODES - 1 : v;
}
// inline dtype probe (first 16 int64 reads; int32 data packed as int64 -> huge)
__device__ __forceinline__ int probe_is32(const void* ei) {
    const long long* p = (const long long*)ei;
    int bad = 0;
#pragma unroll
    for (int j = 0; j < 16; j++) {
        long long v = p[j];
        bad |= (v < 0 || v >= (long long)N_NODES);
    }
    return bad;
}

// ---------------- 1. count (2 edges/thread) + W1 transpose ----------------
__global__ void k_count_w1t(const void* __restrict__ ei, const float* __restrict__ W1) {
    if (blockIdx.x < NE2_BLOCKS) {
        __shared__ int s32;
        if (threadIdx.x == 0) s32 = probe_is32(ei);
        __syncthreads();
        int e2 = (blockIdx.x * 256 + threadIdx.x) * 2;
        if (e2 >= N_EDGES) return;
        int d0, d1;
        if (s32) {
            int2 dd = *(const int2*)((const int*)ei + N_EDGES + e2);
            d0 = dd.x; d1 = dd.y;
        } else {
            longlong2 dd = *(const longlong2*)((const long long*)ei + N_EDGES + e2);
            d0 = (int)dd.x; d1 = (int)dd.y;
        }
        atomicAdd(&g_cnt[clampi(d0)], 1);
        atomicAdd(&g_cnt[clampi(d1)], 1);
    } else {
        int idx = (blockIdx.x - NE2_BLOCKS) * 256 + threadIdx.x;  // < 65536
        int n = idx >> 7;
        int k = idx & 127;
        g_W1T_h[idx] = __float2half_rn(W1[(size_t)k * NH + n]);
    }
}

// ---------------- 2. single-kernel scan + dinv ----------------
__global__ void k_scan() {
    __shared__ int sh[256];
    int b = blockIdx.x, t = threadIdx.x;
    // phase 1: boff = sum cnt[0 .. b*256)  (cooperative)
    int s = 0;
    for (int idx = t; idx < b * 256; idx += 256) s += g_cnt[idx];
    sh[t] = s;
    __syncthreads();
#pragma unroll
    for (int off = 128; off > 0; off >>= 1) {
        if (t < off) sh[t] += sh[t + off];
        __syncthreads();
    }
    int boff = sh[0];
    __syncthreads();
    // phase 2: inclusive scan of own 256 counts
    int idx = b * 256 + t;
    int c = (idx < N_NODES) ? g_cnt[idx] : 0;
    sh[t] = c;
    __syncthreads();
#pragma unroll
    for (int off = 1; off < 256; off <<= 1) {
        int u = (t >= off) ? sh[t - off] : 0;
        __syncthreads();
        sh[t] += u;
        __syncthreads();
    }
    if (idx < N_NODES) {
        int excl = sh[t] - c + boff;
        g_rowptr[idx] = excl;
        g_cursor[idx] = excl;
        g_dinv[idx] = rsqrtf((float)c + 1.0f);
    }
    if (b == 0 && t == 0) g_rowptr[N_NODES] = N_EDGES;
}

// ---------------- 3. scatter + Xs = dinv*X fp16 + cnt restore -------------
__global__ void k_scatter_xs(const void* __restrict__ ei, const float* __restrict__ X) {
    if (blockIdx.x < NE2_BLOCKS) {
        __shared__ int s32;
        if (threadIdx.x == 0) s32 = probe_is32(ei);
        __syncthreads();
        int e2 = (blockIdx.x * 256 + threadIdx.x) * 2;
        if (e2 >= N_EDGES) return;
        int s0, s1, d0, d1;
        if (s32) {
            int2 ss = *(const int2*)((const int*)ei + e2);
            int2 dd = *(const int2*)((const int*)ei + N_EDGES + e2);
            s0 = ss.x; s1 = ss.y; d0 = dd.x; d1 = dd.y;
        } else {
            longlong2 ss = *(const longlong2*)((const long long*)ei + e2);
            longlong2 dd = *(const longlong2*)((const long long*)ei + N_EDGES + e2);
            s0 = (int)ss.x; s1 = (int)ss.y; d0 = (int)dd.x; d1 = (int)dd.y;
        }
        int p0 = atomicAdd(&g_cursor[clampi(d0)], 1);
        g_col[p0] = clampi(s0);
        int p1 = atomicAdd(&g_cursor[clampi(d1)], 1);
        g_col[p1] = clampi(s1);
    } else if (blockIdx.x < NE2_BLOCKS + XS_BLOCKS) {
        int idx4 = ((blockIdx.x - NE2_BLOCKS) * 256 + threadIdx.x) * 4;
        float di = g_dinv[idx4 >> 7];
        float4 v = *(const float4*)&X[idx4];
        __half h[4] = {__float2half_rn(di * v.x), __float2half_rn(di * v.y),
                       __float2half_rn(di * v.z), __float2half_rn(di * v.w)};
        *(uint2*)&g_Xs_h[idx4] = *(uint2*)h;
    } else {
        // restore cnt=0 for the next invocation (cnt is dead after k_scan)
        int i = (blockIdx.x - NE2_BLOCKS - XS_BLOCKS) * 256 + threadIdx.x;
        if (i < N_NODES) g_cnt[i] = 0;
    }
}

// ---------------- 4. AX aggregate (warp/node, fp16 gather, MLP=4) ---------
__global__ void __launch_bounds__(256) k_agg1() {
    int gw = (blockIdx.x * blockDim.x + threadIdx.x) >> 5;
    int lane = threadIdx.x & 31;
    if (gw >= N_NODES) return;
    int i = gw;
    int e0 = g_rowptr[i], e1 = g_rowptr[i + 1];
    float acc0 = 0.f, acc1 = 0.f, acc2 = 0.f, acc3 = 0.f;
    int e = e0;
#pragma unroll 1
    for (; e + 4 <= e1; e += 4) {
        int s0 = g_col[e], s1 = g_col[e + 1], s2 = g_col[e + 2], s3 = g_col[e + 3];
        uint2 u0 = ((const uint2*)&g_Xs_h[(size_t)s0 * NF])[lane];
        uint2 u1 = ((const uint2*)&g_Xs_h[(size_t)s1 * NF])[lane];
        uint2 u2 = ((const uint2*)&g_Xs_h[(size_t)s2 * NF])[lane];
        uint2 u3 = ((const uint2*)&g_Xs_h[(size_t)s3 * NF])[lane];
        float2 a, bb;
        a = __half22float2(*(half2*)&u0.x); bb = __half22float2(*(half2*)&u0.y);
        acc0 += a.x; acc1 += a.y; acc2 += bb.x; acc3 += bb.y;
        a = __half22float2(*(half2*)&u1.x); bb = __half22float2(*(half2*)&u1.y);
        acc0 += a.x; acc1 += a.y; acc2 += bb.x; acc3 += bb.y;
        a = __half22float2(*(half2*)&u2.x); bb = __half22float2(*(half2*)&u2.y);
        acc0 += a.x; acc1 += a.y; acc2 += bb.x; acc3 += bb.y;
        a = __half22float2(*(half2*)&u3.x); bb = __half22float2(*(half2*)&u3.y);
        acc0 += a.x; acc1 += a.y; acc2 += bb.x; acc3 += bb.y;
    }
#pragma unroll 1
    for (; e < e1; e++) {
        int s0 = g_col[e];
        uint2 u0 = ((const uint2*)&g_Xs_h[(size_t)s0 * NF])[lane];
        float2 a = __half22float2(*(half2*)&u0.x);
        float2 bb = __half22float2(*(half2*)&u0.y);
        acc0 += a.x; acc1 += a.y; acc2 += bb.x; acc3 += bb.y;
    }
    uint2 us = ((const uint2*)&g_Xs_h[(size_t)i * NF])[lane];
    float2 s01 = __half22float2(*(half2*)&us.x);
    float2 s23 = __half22float2(*(half2*)&us.y);
    float di = g_dinv[i];
    float v[4] = {di * (acc0 + s01.x), di * (acc1 + s01.y),
                  di * (acc2 + s23.x), di * (acc3 + s23.y)};
    __half h[4];
#pragma unroll
    for (int j = 0; j < 4; j++) h[j] = __float2half_rn(v[j]);
    *(uint2*)&g_AX_h[(size_t)i * NF + lane * 4] = *(uint2*)h;
}

// ---------------- 5. fused GEMM1 (fp16 1-term, M-tile 128) + epilogue -----
#define SM_STRIDE 136
#define SMS (SM_STRIDE * 2)            // 272 B per row
#define TILE_B (128 * SMS)             // 34816 B
#define OFF_A    0
#define OFF_B0   TILE_B
#define OFF_B1   (2 * TILE_B)
#define OFF_CB1  (3 * TILE_B)
#define OFF_CW2X (OFF_CB1 + 2048)
#define OFF_CW2Y (OFF_CW2X + 2048)
#define OFF_RED  (OFF_CW2Y + 2048)
#define SMEM_BYTES (OFF_RED + 1024)

#define LDMX4(r0, r1, r2, r3, addr) \
    asm volatile("ldmatrix.sync.aligned.m8n8.x4.shared.b16 {%0,%1,%2,%3}, [%4];" \
        : "=r"(r0), "=r"(r1), "=r"(r2), "=r"(r3) : "r"(addr))

#define MMA16816(d, a, b) \
    asm volatile("mma.sync.aligned.m16n8k16.row.col.f32.f16.f16.f32 " \
        "{%0,%1,%2,%3}, {%4,%5,%6,%7}, {%8,%9}, {%0,%1,%2,%3};" \
        : "+f"((d)[0]), "+f"((d)[1]), "+f"((d)[2]), "+f"((d)[3]) \
        : "r"((a)[0]), "r"((a)[1]), "r"((a)[2]), "r"((a)[3]), "r"((b)[0]), "r"((b)[1]))

__device__ __forceinline__ void load_B_async(uint32_t sb, int nb, int buf, int tid) {
    int row = tid >> 1;
    int half = tid & 1;
    const char* src = (const char*)&g_W1T_h[(size_t)(nb * 128 + row) * NF + half * 64];
    uint32_t base = sb + (buf ? OFF_B1 : OFF_B0) + (uint32_t)row * SMS + half * 128;
#pragma unroll
    for (int i = 0; i < 8; i++) cp16(base + i * 16, src + i * 16, 16);
}

__global__ void __launch_bounds__(256) k_gemm1_mma(const float* __restrict__ b1,
                                                   const float* __restrict__ W2) {
    extern __shared__ char smem[];
    const uint32_t sb = smem_u32(smem);
    const int tid  = threadIdx.x;
    const int lane = tid & 31;
    const int wid  = tid >> 5;
    const int wm   = wid & 3;
    const int wn   = wid >> 2;
    const int m0   = blockIdx.x * 128;

    {
        int row = tid >> 1;
        int half = tid & 1;
        int gr = m0 + row;
        int ok = (gr < N_NODES) ? 16 : 0;
        int grc = (gr < N_NODES) ? gr : 0;
        const char* srcA = (const char*)&g_AX_h[(size_t)grc * NF + half * 64];
        uint32_t dA = sb + OFF_A + (uint32_t)row * SMS + half * 128;
#pragma unroll
        for (int i = 0; i < 8; i++) cp16(dA + i * 16, srcA + i * 16, ok);
    }
    load_B_async(sb, 0, 0, tid);
    for (int i = tid; i < 512; i += 256) {
        ((float*)(smem + OFF_CB1))[i]  = b1[i];
        ((float*)(smem + OFF_CW2X))[i] = W2[i * 2 + 0];
        ((float*)(smem + OFF_CW2Y))[i] = W2[i * 2 + 1];
    }
    CP_COMMIT();
    CP_WAIT0();
    __syncthreads();

    const int a_row_in16 = lane & 15;
    const int a_k_half   = (lane >> 4) & 1;
    const int b_n_off    = (lane & 7) + ((lane & 16) ? 8 : 0);
    const int b_k_half   = (lane & 8) ? 1 : 0;
    const float* sB1  = (const float*)(smem + OFF_CB1);
    const float* sW2x = (const float*)(smem + OFF_CW2X);
    const float* sW2y = (const float*)(smem + OFF_CW2Y);
    const int g = lane >> 2;
    const int q = lane & 3;

    float p0[2][2], p1[2][2];
#pragma unroll
    for (int mt = 0; mt < 2; mt++)
#pragma unroll
        for (int rh = 0; rh < 2; rh++) { p0[mt][rh] = 0.f; p1[mt][rh] = 0.f; }

#pragma unroll 1
    for (int nb = 0; nb < 4; nb++) {
        if (nb < 3) { load_B_async(sb, nb + 1, (nb + 1) & 1, tid); CP_COMMIT(); }
        const uint32_t bbase = sb + ((nb & 1) ? OFF_B1 : OFF_B0);

        float d[2][8][4];
#pragma unroll
        for (int mt = 0; mt < 2; mt++)
#pragma unroll
            for (int nt = 0; nt < 8; nt++)
#pragma unroll
                for (int j = 0; j < 4; j++) d[mt][nt][j] = 0.0f;

#pragma unroll 1
        for (int k0 = 0; k0 < 128; k0 += 16) {
            uint32_t ah[2][4];
#pragma unroll
            for (int mt = 0; mt < 2; mt++) {
                int r = wm * 32 + mt * 16 + a_row_in16;
                uint32_t col = (uint32_t)(k0 + a_k_half * 8) * 2;
                LDMX4(ah[mt][0], ah[mt][1], ah[mt][2], ah[mt][3],
                      sb + OFF_A + (uint32_t)r * SMS + col);
            }
            uint32_t bh[8][2];
#pragma unroll
            for (int np = 0; np < 4; np++) {
                int nrow = wn * 64 + np * 16 + b_n_off;
                uint32_t col = (uint32_t)(k0 + b_k_half * 8) * 2;
                uint32_t r0, r1, r2, r3;
                LDMX4(r0, r1, r2, r3, bbase + (uint32_t)nrow * SMS + col);
                bh[np * 2][0] = r0; bh[np * 2][1] = r1;
                bh[np * 2 + 1][0] = r2; bh[np * 2 + 1][1] = r3;
            }
#pragma unroll
            for (int mt = 0; mt < 2; mt++)
#pragma unroll
                for (int nt = 0; nt < 8; nt++)
                    MMA16816(d[mt][nt], ah[mt], bh[nt]);
        }

#pragma unroll
        for (int mt = 0; mt < 2; mt++)
#pragma unroll
            for (int rh = 0; rh < 2; rh++)
#pragma unroll
                for (int nt = 0; nt < 8; nt++)
#pragma unroll
                    for (int j = 0; j < 2; j++) {
                        int col = nb * 128 + wn * 64 + nt * 8 + q * 2 + j;
                        float v = d[mt][nt][rh * 2 + j] + sB1[col];
                        v = fmaxf(v, 0.0f);
                        p0[mt][rh] += v * sW2x[col];
                        p1[mt][rh] += v * sW2y[col];
                    }

        if (nb < 3) { CP_WAIT0(); __syncthreads(); }
    }

    float pr0[2][2], pr1[2][2];
#pragma unroll
    for (int mt = 0; mt < 2; mt++)
#pragma unroll
        for (int rh = 0; rh < 2; rh++) {
            float a = p0[mt][rh], b = p1[mt][rh];
            a += __shfl_xor_sync(0xFFFFFFFFu, a, 1);
            b += __shfl_xor_sync(0xFFFFFFFFu, b, 1);
            a += __shfl_xor_sync(0xFFFFFFFFu, a, 2);
            b += __shfl_xor_sync(0xFFFFFFFFu, b, 2);
            pr0[mt][rh] = a; pr1[mt][rh] = b;
        }
    float2* red = (float2*)(smem + OFF_RED);
    __syncthreads();
    if (wn == 1 && q == 0) {
#pragma unroll
        for (int mt = 0; mt < 2; mt++)
#pragma unroll
            for (int rh = 0; rh < 2; rh++) {
                int lr = wm * 32 + mt * 16 + rh * 8 + g;
                red[lr] = make_float2(pr0[mt][rh], pr1[mt][rh]);
            }
    }
    __syncthreads();
    if (wn == 0 && q == 0) {
#pragma unroll
        for (int mt = 0; mt < 2; mt++)
#pragma unroll
            for (int rh = 0; rh < 2; rh++) {
                int lr = wm * 32 + mt * 16 + rh * 8 + g;
                int row = m0 + lr;
                if (row < N_NODES) {
                    float2 o = red[lr];
                    float di = g_dinv[row];
                    g_HW2[row] = make_float2(di * (pr0[mt][rh] + o.x),
                                             di * (pr1[mt][rh] + o.y));
                }
            }
    }
}

// ---------------- 6. aggregate layer2 (warp/node) + softmax ----------------
__global__ void __launch_bounds__(256) k_agg2(const float* __restrict__ b2,
                                              float* __restrict__ out) {
    int gw = (blockIdx.x * blockDim.x + threadIdx.x) >> 5;
    int lane = threadIdx.x & 31;
    if (gw >= N_NODES) return;
    int i = gw;
    int e0 = g_rowptr[i], e1 = g_rowptr[i + 1];
    float a0 = 0.f, a1 = 0.f;
    for (int e = e0 + lane; e < e1; e += 32) {
        float2 m = g_HW2[g_col[e]];
        a0 += m.x;
        a1 += m.y;
    }
#pragma unroll
    for (int off = 16; off > 0; off >>= 1) {
        a0 += __shfl_xor_sync(0xFFFFFFFFu, a0, off);
        a1 += __shfl_xor_sync(0xFFFFFFFFu, a1, off);
    }
    if (lane == 0) {
        float di = g_dinv[i];
        float2 self = g_HW2[i];
        float l0 = di * (a0 + self.x) + b2[0];
        float l1 = di * (a1 + self.y) + b2[1];
        float mx = fmaxf(l0, l1);
        float e0f = __expf(l0 - mx);
        float e1f = __expf(l1 - mx);
        float inv = 1.0f / (e0f + e1f);
        out[(size_t)i * 2 + 0] = e0f * inv;
        out[(size_t)i * 2 + 1] = e1f * inv;
    }
}

// ---------------- launch ----------------
extern "C" void kernel_launch(void* const* d_in, const int* in_sizes, int n_in,
                              void* d_out, int out_size) {
    const float* X  = (const float*)d_in[0];
    const void*  EI = d_in[1];
    const float* W1 = (const float*)d_in[2];
    const float* b1 = (const float*)d_in[3];
    const float* W2 = (const float*)d_in[4];
    const float* b2 = (const float*)d_in[5];
    float* out = (float*)d_out;
    (void)in_sizes; (void)n_in; (void)out_size;

    cudaFuncSetAttribute(k_gemm1_mma, cudaFuncAttributeMaxDynamicSharedMemorySize, SMEM_BYTES);

    k_count_w1t<<<NE2_BLOCKS + W1T_BLOCKS, 256>>>(EI, W1);
    k_scan<<<NBLK, 256>>>();
    k_scatter_xs<<<NE2_BLOCKS + XS_BLOCKS + NBLK, 256>>>(EI, X);
    k_agg1<<<(N_NODES * 32 + 255) / 256, 256>>>();
    k_gemm1_mma<<<(N_NODES + 127) / 128, 256, SMEM_BYTES>>>(b1, W2);
    k_agg2<<<(N_NODES * 32 + 255) / 256, 256>>>(b2, out);
}

// round 15
// speedup vs baseline: 1.0329x; 1.0329x over previous
#include <cuda_runtime.h>
#include <cuda_fp16.h>
#include <math.h>
#include <stdint.h>

#define N_NODES 50000
#define N_EDGES 800000
#define NF 128
#define NH 512
#define NBLK 196               // ceil(50000/256)
#define NE2_BLOCKS 1563        // ceil((800000/2)/256)
#define W1T_BLOCKS 256         // 65536/256
#define XS_BLOCKS 6250         // (50000*128/4)/256

// ---------------- scratch (device globals; zero-initialized at load) ------
__device__ float g_dinv[N_NODES];
__device__ int   g_cnt[N_NODES];       // ALWAYS zero at kernel_launch entry
__device__ int   g_rowptr[N_NODES + 1];
__device__ int   g_cursor[N_NODES];
__device__ int   g_col[N_EDGES];
__device__ int   g_bsum[NBLK];
__device__ __align__(16) __half g_Xs_h[(size_t)N_NODES * NF];   // dinv*X fp16
__device__ __align__(16) __half g_AX_h[(size_t)N_NODES * NF];
__device__ __align__(16) __half g_W1T_h[(size_t)NH * NF];
__device__ float2 g_HW2[N_NODES];

__device__ __forceinline__ uint32_t smem_u32(const void* p) {
    uint32_t a;
    asm("{ .reg .u64 t; cvta.to.shared.u64 t, %1; cvt.u32.u64 %0, t; }" : "=r"(a) : "l"(p));
    return a;
}
__device__ __forceinline__ void cp16(uint32_t dst, const void* src, int sz) {
    asm volatile("cp.async.cg.shared.global [%0], [%1], 16, %2;"
                 :: "r"(dst), "l"(src), "r"(sz));
}
#define CP_COMMIT() asm volatile("cp.async.commit_group;" ::: "memory")
#define CP_WAIT0()  asm volatile("cp.async.wait_group 0;" ::: "memory")

__device__ __forceinline__ int clampi(int v) {
    v = v < 0 ? 0 : v;
    return v >= N_NODES ? N_NODES - 1 : v;
}
// inline dtype probe (first 16 int64 reads; int32 data packed as int64 -> huge)
__device__ __forceinline__ int probe_is32(const void* ei) {
    const long long* p = (const long long*)ei;
    int bad = 0;
#pragma unroll
    for (int j = 0; j < 16; j++) {
        long long v = p[j];
        bad |= (v < 0 || v >= (long long)N_NODES);
    }
    return bad;
}

// ---------------- 1. count (2 edges/thread) + W1 transpose ----------------
__global__ void k_count_w1t(const void* __restrict__ ei, const float* __restrict__ W1) {
    if (blockIdx.x < NE2_BLOCKS) {
        __shared__ int s32;
        if (threadIdx.x == 0) s32 = probe_is32(ei);
        __syncthreads();
        int e2 = (blockIdx.x * 256 + threadIdx.x) * 2;
        if (e2 >= N_EDGES) return;
        int d0, d1;
        if (s32) {
            int2 dd = *(const int2*)((const int*)ei + N_EDGES + e2);
            d0 = dd.x; d1 = dd.y;
        } else {
            longlong2 dd = *(const longlong2*)((const long long*)ei + N_EDGES + e2);
            d0 = (int)dd.x; d1 = (int)dd.y;
        }
        atomicAdd(&g_cnt[clampi(d0)], 1);
        atomicAdd(&g_cnt[clampi(d1)], 1);
    } else {
        int idx = (blockIdx.x - NE2_BLOCKS) * 256 + threadIdx.x;  // < 65536
        int n = idx >> 7;
        int k = idx & 127;
        g_W1T_h[idx] = __float2half_rn(W1[(size_t)k * NH + n]);
    }
}

// ---------------- 2. block sums ----------------
__global__ void k_bsum() {
    __shared__ int sh[256];
    int idx = blockIdx.x * 256 + threadIdx.x;
    int c = (idx < N_NODES) ? g_cnt[idx] : 0;
    sh[threadIdx.x] = c;
    __syncthreads();
#pragma unroll
    for (int off = 128; off > 0; off >>= 1) {
        if (threadIdx.x < off) sh[threadIdx.x] += sh[threadIdx.x + off];
        __syncthreads();
    }
    if (threadIdx.x == 0) g_bsum[blockIdx.x] = sh[0];
}

// ---------------- 3. scan (root inlined) + dinv ----------------
__global__ void k_bscan() {
    __shared__ int sh[256];
    int b = blockIdx.x, t = threadIdx.x;
    int v = (t < NBLK) ? g_bsum[t] : 0;
    sh[t] = v;
    __syncthreads();
#pragma unroll
    for (int off = 1; off < 256; off <<= 1) {
        int u = (t >= off) ? sh[t - off] : 0;
        __syncthreads();
        sh[t] += u;
        __syncthreads();
    }
    int boff = (b == 0) ? 0 : sh[b - 1];
    __syncthreads();
    int idx = b * 256 + t;
    int c = (idx < N_NODES) ? g_cnt[idx] : 0;
    sh[t] = c;
    __syncthreads();
#pragma unroll
    for (int off = 1; off < 256; off <<= 1) {
        int u = (t >= off) ? sh[t - off] : 0;
        __syncthreads();
        sh[t] += u;
        __syncthreads();
    }
    if (idx < N_NODES) {
        int excl = sh[t] - c + boff;
        g_rowptr[idx] = excl;
        g_cursor[idx] = excl;
        g_dinv[idx] = rsqrtf((float)c + 1.0f);
    }
    if (b == 0 && t == 0) g_rowptr[N_NODES] = N_EDGES;
}

// ---------------- 4. scatter + Xs = dinv*X fp16 + cnt restore -------------
__global__ void k_scatter_xs(const void* __restrict__ ei, const float* __restrict__ X) {
    if (blockIdx.x < NE2_BLOCKS) {
        __shared__ int s32;
        if (threadIdx.x == 0) s32 = probe_is32(ei);
        __syncthreads();
        int e2 = (blockIdx.x * 256 + threadIdx.x) * 2;
        if (e2 >= N_EDGES) return;
        int s0, s1, d0, d1;
        if (s32) {
            int2 ss = *(const int2*)((const int*)ei + e2);
            int2 dd = *(const int2*)((const int*)ei + N_EDGES + e2);
            s0 = ss.x; s1 = ss.y; d0 = dd.x; d1 = dd.y;
        } else {
            longlong2 ss = *(const longlong2*)((const long long*)ei + e2);
            longlong2 dd = *(const longlong2*)((const long long*)ei + N_EDGES + e2);
            s0 = (int)ss.x; s1 = (int)ss.y; d0 = (int)dd.x; d1 = (int)dd.y;
        }
        int p0 = atomicAdd(&g_cursor[clampi(d0)], 1);
        g_col[p0] = clampi(s0);
        int p1 = atomicAdd(&g_cursor[clampi(d1)], 1);
        g_col[p1] = clampi(s1);
    } else if (blockIdx.x < NE2_BLOCKS + XS_BLOCKS) {
        int idx4 = ((blockIdx.x - NE2_BLOCKS) * 256 + threadIdx.x) * 4;
        float di = g_dinv[idx4 >> 7];
        float4 v = *(const float4*)&X[idx4];
        __half h[4] = {__float2half_rn(di * v.x), __float2half_rn(di * v.y),
                       __float2half_rn(di * v.z), __float2half_rn(di * v.w)};
        *(uint2*)&g_Xs_h[idx4] = *(uint2*)h;
    } else {
        // restore cnt=0 for the next invocation (cnt is dead after k_bscan)
        int i = (blockIdx.x - NE2_BLOCKS - XS_BLOCKS) * 256 + threadIdx.x;
        if (i < N_NODES) g_cnt[i] = 0;
    }
}

// ---------------- 5. AX aggregate (warp/node, fp16 gather, MLP=4) ---------
__global__ void __launch_bounds__(256) k_agg1() {
    int gw = (blockIdx.x * blockDim.x + threadIdx.x) >> 5;
    int lane = threadIdx.x & 31;
    if (gw >= N_NODES) return;
    int i = gw;
    int e0 = g_rowptr[i], e1 = g_rowptr[i + 1];
    float acc0 = 0.f, acc1 = 0.f, acc2 = 0.f, acc3 = 0.f;
    int e = e0;
#pragma unroll 1
    for (; e + 4 <= e1; e += 4) {
        int s0 = g_col[e], s1 = g_col[e + 1], s2 = g_col[e + 2], s3 = g_col[e + 3];
        uint2 u0 = ((const uint2*)&g_Xs_h[(size_t)s0 * NF])[lane];
        uint2 u1 = ((const uint2*)&g_Xs_h[(size_t)s1 * NF])[lane];
        uint2 u2 = ((const uint2*)&g_Xs_h[(size_t)s2 * NF])[lane];
        uint2 u3 = ((const uint2*)&g_Xs_h[(size_t)s3 * NF])[lane];
        float2 a, bb;
        a = __half22float2(*(half2*)&u0.x); bb = __half22float2(*(half2*)&u0.y);
        acc0 += a.x; acc1 += a.y; acc2 += bb.x; acc3 += bb.y;
        a = __half22float2(*(half2*)&u1.x); bb = __half22float2(*(half2*)&u1.y);
        acc0 += a.x; acc1 += a.y; acc2 += bb.x; acc3 += bb.y;
        a = __half22float2(*(half2*)&u2.x); bb = __half22float2(*(half2*)&u2.y);
        acc0 += a.x; acc1 += a.y; acc2 += bb.x; acc3 += bb.y;
        a = __half22float2(*(half2*)&u3.x); bb = __half22float2(*(half2*)&u3.y);
        acc0 += a.x; acc1 += a.y; acc2 += bb.x; acc3 += bb.y;
    }
#pragma unroll 1
    for (; e < e1; e++) {
        int s0 = g_col[e];
        uint2 u0 = ((const uint2*)&g_Xs_h[(size_t)s0 * NF])[lane];
        float2 a = __half22float2(*(half2*)&u0.x);
        float2 bb = __half22float2(*(half2*)&u0.y);
        acc0 += a.x; acc1 += a.y; acc2 += bb.x; acc3 += bb.y;
    }
    uint2 us = ((const uint2*)&g_Xs_h[(size_t)i * NF])[lane];
    float2 s01 = __half22float2(*(half2*)&us.x);
    float2 s23 = __half22float2(*(half2*)&us.y);
    float di = g_dinv[i];
    float v[4] = {di * (acc0 + s01.x), di * (acc1 + s01.y),
                  di * (acc2 + s23.x), di * (acc3 + s23.y)};
    __half h[4];
#pragma unroll
    for (int j = 0; j < 4; j++) h[j] = __float2half_rn(v[j]);
    *(uint2*)&g_AX_h[(size_t)i * NF + lane * 4] = *(uint2*)h;
}

// ---------------- 6. fused GEMM1 (fp16 1-term, M-tile 128) + epilogue -----
#define SM_STRIDE 136
#define SMS (SM_STRIDE * 2)            // 272 B per row
#define TILE_B (128 * SMS)             // 34816 B
#define OFF_A    0
#define OFF_B0   TILE_B
#define OFF_B1   (2 * TILE_B)
#define OFF_CB1  (3 * TILE_B)
#define OFF_CW2X (OFF_CB1 + 2048)
#define OFF_CW2Y (OFF_CW2X + 2048)
#define OFF_RED  (OFF_CW2Y + 2048)
#define SMEM_BYTES (OFF_RED + 1024)

#define LDMX4(r0, r1, r2, r3, addr) \
    asm volatile("ldmatrix.sync.aligned.m8n8.x4.shared.b16 {%0,%1,%2,%3}, [%4];" \
        : "=r"(r0), "=r"(r1), "=r"(r2), "=r"(r3) : "r"(addr))

#define MMA16816(d, a, b) \
    asm volatile("mma.sync.aligned.m16n8k16.row.col.f32.f16.f16.f32 " \
        "{%0,%1,%2,%3}, {%4,%5,%6,%7}, {%8,%9}, {%0,%1,%2,%3};" \
        : "+f"((d)[0]), "+f"((d)[1]), "+f"((d)[2]), "+f"((d)[3]) \
        : "r"((a)[0]), "r"((a)[1]), "r"((a)[2]), "r"((a)[3]), "r"((b)[0]), "r"((b)[1]))

__device__ __forceinline__ void load_B_async(uint32_t sb, int nb, int buf, int tid) {
    int row = tid >> 1;
    int half = tid & 1;
    const char* src = (const char*)&g_W1T_h[(size_t)(nb * 128 + row) * NF + half * 64];
    uint32_t base = sb + (buf ? OFF_B1 : OFF_B0) + (uint32_t)row * SMS + half * 128;
#pragma unroll
    for (int i = 0; i < 8; i++) cp16(base + i * 16, src + i * 16, 16);
}

__global__ void __launch_bounds__(256) k_gemm1_mma(const float* __restrict__ b1,
                                                   const float* __restrict__ W2) {
    extern __shared__ char smem[];
    const uint32_t sb = smem_u32(smem);
    const int tid  = threadIdx.x;
    const int lane = tid & 31;
    const int wid  = tid >> 5;
    const int wm   = wid & 3;
    const int wn   = wid >> 2;
    const int m0   = blockIdx.x * 128;

    {
        int row = tid >> 1;
        int half = tid & 1;
        int gr = m0 + row;
        int ok = (gr < N_NODES) ? 16 : 0;
        int grc = (gr < N_NODES) ? gr : 0;
        const char* srcA = (const char*)&g_AX_h[(size_t)grc * NF + half * 64];
        uint32_t dA = sb + OFF_A + (uint32_t)row * SMS + half * 128;
#pragma unroll
        for (int i = 0; i < 8; i++) cp16(dA + i * 16, srcA + i * 16, ok);
    }
    load_B_async(sb, 0, 0, tid);
    for (int i = tid; i < 512; i += 256) {
        ((float*)(smem + OFF_CB1))[i]  = b1[i];
        ((float*)(smem + OFF_CW2X))[i] = W2[i * 2 + 0];
        ((float*)(smem + OFF_CW2Y))[i] = W2[i * 2 + 1];
    }
    CP_COMMIT();
    CP_WAIT0();
    __syncthreads();

    const int a_row_in16 = lane & 15;
    const int a_k_half   = (lane >> 4) & 1;
    const int b_n_off    = (lane & 7) + ((lane & 16) ? 8 : 0);
    const int b_k_half   = (lane & 8) ? 1 : 0;
    const float* sB1  = (const float*)(smem + OFF_CB1);
    const float* sW2x = (const float*)(smem + OFF_CW2X);
    const float* sW2y = (const float*)(smem + OFF_CW2Y);
    const int g = lane >> 2;
    const int q = lane & 3;

    float p0[2][2], p1[2][2];
#pragma unroll
    for (int mt = 0; mt < 2; mt++)
#pragma unroll
        for (int rh = 0; rh < 2; rh++) { p0[mt][rh] = 0.f; p1[mt][rh] = 0.f; }

#pragma unroll 1
    for (int nb = 0; nb < 4; nb++) {
        if (nb < 3) { load_B_async(sb, nb + 1, (nb + 1) & 1, tid); CP_COMMIT(); }
        const uint32_t bbase = sb + ((nb & 1) ? OFF_B1 : OFF_B0);

        float d[2][8][4];
#pragma unroll
        for (int mt = 0; mt < 2; mt++)
#pragma unroll
            for (int nt = 0; nt < 8; nt++)
#pragma unroll
                for (int j = 0; j < 4; j++) d[mt][nt][j] = 0.0f;

#pragma unroll 1
        for (int k0 = 0; k0 < 128; k0 += 16) {
            uint32_t ah[2][4];
#pragma unroll
            for (int mt = 0; mt < 2; mt++) {
                int r = wm * 32 + mt * 16 + a_row_in16;
                uint32_t col = (uint32_t)(k0 + a_k_half * 8) * 2;
                LDMX4(ah[mt][0], ah[mt][1], ah[mt][2], ah[mt][3],
                      sb + OFF_A + (uint32_t)r * SMS + col);
            }
            uint32_t bh[8][2];
#pragma unroll
            for (int np = 0; np < 4; np++) {
                int nrow = wn * 64 + np * 16 + b_n_off;
                uint32_t col = (uint32_t)(k0 + b_k_half * 8) * 2;
                uint32_t r0, r1, r2, r3;
                LDMX4(r0, r1, r2, r3, bbase + (uint32_t)nrow * SMS + col);
                bh[np * 2][0] = r0; bh[np * 2][1] = r1;
                bh[np * 2 + 1][0] = r2; bh[np * 2 + 1][1] = r3;
            }
#pragma unroll
            for (int mt = 0; mt < 2; mt++)
#pragma unroll
                for (int nt = 0; nt < 8; nt++)
                    MMA16816(d[mt][nt], ah[mt], bh[nt]);
        }

#pragma unroll
        for (int mt = 0; mt < 2; mt++)
#pragma unroll
            for (int rh = 0; rh < 2; rh++)
#pragma unroll
                for (int nt = 0; nt < 8; nt++)
#pragma unroll
                    for (int j = 0; j < 2; j++) {
                        int col = nb * 128 + wn * 64 + nt * 8 + q * 2 + j;
                        float v = d[mt][nt][rh * 2 + j] + sB1[col];
                        v = fmaxf(v, 0.0f);
                        p0[mt][rh] += v * sW2x[col];
                        p1[mt][rh] += v * sW2y[col];
                    }

        if (nb < 3) { CP_WAIT0(); __syncthreads(); }
    }

    float pr0[2][2], pr1[2][2];
#pragma unroll
    for (int mt = 0; mt < 2; mt++)
#pragma unroll
        for (int rh = 0; rh < 2; rh++) {
            float a = p0[mt][rh], b = p1[mt][rh];
            a += __shfl_xor_sync(0xFFFFFFFFu, a, 1);
            b += __shfl_xor_sync(0xFFFFFFFFu, b, 1);
            a += __shfl_xor_sync(0xFFFFFFFFu, a, 2);
            b += __shfl_xor_sync(0xFFFFFFFFu, b, 2);
            pr0[mt][rh] = a; pr1[mt][rh] = b;
        }
    float2* red = (float2*)(smem + OFF_RED);
    __syncthreads();
    if (wn == 1 && q == 0) {
#pragma unroll
        for (int mt = 0; mt < 2; mt++)
#pragma unroll
            for (int rh = 0; rh < 2; rh++) {
                int lr = wm * 32 + mt * 16 + rh * 8 + g;
                red[lr] = make_float2(pr0[mt][rh], pr1[mt][rh]);
            }
    }
    __syncthreads();
    if (wn == 0 && q == 0) {
#pragma unroll
        for (int mt = 0; mt < 2; mt++)
#pragma unroll
            for (int rh = 0; rh < 2; rh++) {
                int lr = wm * 32 + mt * 16 + rh * 8 + g;
                int row = m0 + lr;
                if (row < N_NODES) {
                    float2 o = red[lr];
                    float di = g_dinv[row];
                    g_HW2[row] = make_float2(di * (pr0[mt][rh] + o.x),
                                             di * (pr1[mt][rh] + o.y));
                }
            }
    }
}

// ---------------- 7. aggregate layer2 (warp/node) + softmax ----------------
__global__ void __launch_bounds__(256) k_agg2(const float* __restrict__ b2,
                                              float* __restrict__ out) {
    int gw = (blockIdx.x * blockDim.x + threadIdx.x) >> 5;
    int lane = threadIdx.x & 31;
    if (gw >= N_NODES) return;
    int i = gw;
    int e0 = g_rowptr[i], e1 = g_rowptr[i + 1];
    float a0 = 0.f, a1 = 0.f;
    for (int e = e0 + lane; e < e1; e += 32) {
        float2 m = g_HW2[g_col[e]];
        a0 += m.x;
        a1 += m.y;
    }
#pragma unroll
    for (int off = 16; off > 0; off >>= 1) {
        a0 += __shfl_xor_sync(0xFFFFFFFFu, a0, off);
        a1 += __shfl_xor_sync(0xFFFFFFFFu, a1, off);
    }
    if (lane == 0) {
        float di = g_dinv[i];
        float2 self = g_HW2[i];
        float l0 = di * (a0 + self.x) + b2[0];
        float l1 = di * (a1 + self.y) + b2[1];
        float mx = fmaxf(l0, l1);
        float e0f = __expf(l0 - mx);
        float e1f = __expf(l1 - mx);
        float inv = 1.0f / (e0f + e1f);
        out[(size_t)i * 2 + 0] = e0f * inv;
        out[(size_t)i * 2 + 1] = e1f * inv;
    }
}

// ---------------- launch ----------------
extern "C" void kernel_launch(void* const* d_in, const int* in_sizes, int n_in,
                              void* d_out, int out_size) {
    const float* X  = (const float*)d_in[0];
    const void*  EI = d_in[1];
    const float* W1 = (const float*)d_in[2];
    const float* b1 = (const float*)d_in[3];
    const float* W2 = (const float*)d_in[4];
    const float* b2 = (const float*)d_in[5];
    float* out = (float*)d_out;
    (void)in_sizes; (void)n_in; (void)out_size;

    cudaFuncSetAttribute(k_gemm1_mma, cudaFuncAttributeMaxDynamicSharedMemorySize, SMEM_BYTES);

    k_count_w1t<<<NE2_BLOCKS + W1T_BLOCKS, 256>>>(EI, W1);
    k_bsum<<<NBLK, 256>>>();
    k_bscan<<<NBLK, 256>>>();
    k_scatter_xs<<<NE2_BLOCKS + XS_BLOCKS + NBLK, 256>>>(EI, X);
    k_agg1<<<(N_NODES * 32 + 255) / 256, 256>>>();
    k_gemm1_mma<<<(N_NODES + 127) / 128, 256, SMEM_BYTES>>>(b1, W2);
    k_agg2<<<(N_NODES * 32 + 255) / 256, 256>>>(b2, out);
}

// round 16
// speedup vs baseline: 1.0621x; 1.0283x over previous
#include <cuda_runtime.h>
#include <cuda_fp16.h>
#include <math.h>
#include <stdint.h>

#define N_NODES 50000
#define N_EDGES 800000
#define NF 128
#define NH 512
#define NBLK 196               // ceil(50000/256)
#define NE2_BLOCKS 1563        // ceil((800000/2)/256)
#define W1T_BLOCKS 256         // 65536/256
#define XS_BLOCKS 6250         // (50000*128/4)/256

// ---------------- scratch (device globals; zero-initialized at load) ------
__device__ float g_dinv[N_NODES];
__device__ int   g_cnt[N_NODES];       // ALWAYS zero at kernel_launch entry
__device__ int   g_rowptr[N_NODES + 1];
__device__ int   g_cursor[N_NODES];
__device__ int   g_col[N_EDGES];
__device__ int   g_bsum[NBLK];
__device__ __align__(16) __half g_Xs_h[(size_t)N_NODES * NF];   // dinv*X fp16
__device__ __align__(16) __half g_AX_h[(size_t)N_NODES * NF];
__device__ __align__(16) __half g_W1T_h[(size_t)NH * NF];
__device__ float2 g_HW2[N_NODES];

__device__ __forceinline__ uint32_t smem_u32(const void* p) {
    uint32_t a;
    asm("{ .reg .u64 t; cvta.to.shared.u64 t, %1; cvt.u32.u64 %0, t; }" : "=r"(a) : "l"(p));
    return a;
}
__device__ __forceinline__ void cp16(uint32_t dst, const void* src, int sz) {
    asm volatile("cp.async.cg.shared.global [%0], [%1], 16, %2;"
                 :: "r"(dst), "l"(src), "r"(sz));
}
#define CP_COMMIT() asm volatile("cp.async.commit_group;" ::: "memory")
#define CP_WAIT0()  asm volatile("cp.async.wait_group 0;" ::: "memory")

__device__ __forceinline__ int clampi(int v) {
    v = v < 0 ? 0 : v;
    return v >= N_NODES ? N_NODES - 1 : v;
}
__device__ __forceinline__ int probe_is32(const void* ei) {
    const long long* p = (const long long*)ei;
    int bad = 0;
#pragma unroll
    for (int j = 0; j < 16; j++) {
        long long v = p[j];
        bad |= (v < 0 || v >= (long long)N_NODES);
    }
    return bad;
}

// ---------------- 1. count (2 edges/thread) + W1 transpose ----------------
__global__ void k_count_w1t(const void* __restrict__ ei, const float* __restrict__ W1) {
    if (blockIdx.x < NE2_BLOCKS) {
        __shared__ int s32;
        if (threadIdx.x == 0) s32 = probe_is32(ei);
        __syncthreads();
        int e2 = (blockIdx.x * 256 + threadIdx.x) * 2;
        if (e2 >= N_EDGES) return;
        int d0, d1;
        if (s32) {
            int2 dd = *(const int2*)((const int*)ei + N_EDGES + e2);
            d0 = dd.x; d1 = dd.y;
        } else {
            longlong2 dd = *(const longlong2*)((const long long*)ei + N_EDGES + e2);
            d0 = (int)dd.x; d1 = (int)dd.y;
        }
        atomicAdd(&g_cnt[clampi(d0)], 1);
        atomicAdd(&g_cnt[clampi(d1)], 1);
    } else {
        int idx = (blockIdx.x - NE2_BLOCKS) * 256 + threadIdx.x;  // < 65536
        int n = idx >> 7;
        int k = idx & 127;
        g_W1T_h[idx] = __float2half_rn(W1[(size_t)k * NH + n]);
    }
}

// ---------------- 2. block sums ----------------
__global__ void k_bsum() {
    __shared__ int sh[256];
    int idx = blockIdx.x * 256 + threadIdx.x;
    int c = (idx < N_NODES) ? g_cnt[idx] : 0;
    sh[threadIdx.x] = c;
    __syncthreads();
#pragma unroll
    for (int off = 128; off > 0; off >>= 1) {
        if (threadIdx.x < off) sh[threadIdx.x] += sh[threadIdx.x + off];
        __syncthreads();
    }
    if (threadIdx.x == 0) g_bsum[blockIdx.x] = sh[0];
}

// ---------------- 3. scan (root inlined) + dinv ----------------
__global__ void k_bscan() {
    __shared__ int sh[256];
    int b = blockIdx.x, t = threadIdx.x;
    int v = (t < NBLK) ? g_bsum[t] : 0;
    sh[t] = v;
    __syncthreads();
#pragma unroll
    for (int off = 1; off < 256; off <<= 1) {
        int u = (t >= off) ? sh[t - off] : 0;
        __syncthreads();
        sh[t] += u;
        __syncthreads();
    }
    int boff = (b == 0) ? 0 : sh[b - 1];
    __syncthreads();
    int idx = b * 256 + t;
    int c = (idx < N_NODES) ? g_cnt[idx] : 0;
    sh[t] = c;
    __syncthreads();
#pragma unroll
    for (int off = 1; off < 256; off <<= 1) {
        int u = (t >= off) ? sh[t - off] : 0;
        __syncthreads();
        sh[t] += u;
        __syncthreads();
    }
    if (idx < N_NODES) {
        int excl = sh[t] - c + boff;
        g_rowptr[idx] = excl;
        g_cursor[idx] = excl;
        g_dinv[idx] = rsqrtf((float)c + 1.0f);
    }
    if (b == 0 && t == 0) g_rowptr[N_NODES] = N_EDGES;
}

// ---------------- 4. scatter + Xs = dinv*X fp16 + cnt restore -------------
__global__ void k_scatter_xs(const void* __restrict__ ei, const float* __restrict__ X) {
    if (blockIdx.x < NE2_BLOCKS) {
        __shared__ int s32;
        if (threadIdx.x == 0) s32 = probe_is32(ei);
        __syncthreads();
        int e2 = (blockIdx.x * 256 + threadIdx.x) * 2;
        if (e2 >= N_EDGES) return;
        int s0, s1, d0, d1;
        if (s32) {
            int2 ss = *(const int2*)((const int*)ei + e2);
            int2 dd = *(const int2*)((const int*)ei + N_EDGES + e2);
            s0 = ss.x; s1 = ss.y; d0 = dd.x; d1 = dd.y;
        } else {
            longlong2 ss = *(const longlong2*)((const long long*)ei + e2);
            longlong2 dd = *(const longlong2*)((const long long*)ei + N_EDGES + e2);
            s0 = (int)ss.x; s1 = (int)ss.y; d0 = (int)dd.x; d1 = (int)dd.y;
        }
        int p0 = atomicAdd(&g_cursor[clampi(d0)], 1);
        g_col[p0] = clampi(s0);
        int p1 = atomicAdd(&g_cursor[clampi(d1)], 1);
        g_col[p1] = clampi(s1);
    } else if (blockIdx.x < NE2_BLOCKS + XS_BLOCKS) {
        int idx4 = ((blockIdx.x - NE2_BLOCKS) * 256 + threadIdx.x) * 4;
        float di = g_dinv[idx4 >> 7];
        float4 v = *(const float4*)&X[idx4];
        __half h[4] = {__float2half_rn(di * v.x), __float2half_rn(di * v.y),
                       __float2half_rn(di * v.z), __float2half_rn(di * v.w)};
        *(uint2*)&g_Xs_h[idx4] = *(uint2*)h;
    } else {
        int i = (blockIdx.x - NE2_BLOCKS - XS_BLOCKS) * 256 + threadIdx.x;
        if (i < N_NODES) g_cnt[i] = 0;
    }
}

// ---------------- 5. AX aggregate (warp/node, HADD2-paired) ---------------
__global__ void __launch_bounds__(256) k_agg1() {
    int gw = (blockIdx.x * blockDim.x + threadIdx.x) >> 5;
    int lane = threadIdx.x & 31;
    if (gw >= N_NODES) return;
    int i = gw;
    int e0 = g_rowptr[i], e1 = g_rowptr[i + 1];
    float acc0 = 0.f, acc1 = 0.f, acc2 = 0.f, acc3 = 0.f;
    int e = e0;
#pragma unroll 1
    for (; e + 4 <= e1; e += 4) {
        int s0 = g_col[e], s1 = g_col[e + 1], s2 = g_col[e + 2], s3 = g_col[e + 3];
        uint2 u0 = ((const uint2*)&g_Xs_h[(size_t)s0 * NF])[lane];
        uint2 u1 = ((const uint2*)&g_Xs_h[(size_t)s1 * NF])[lane];
        uint2 u2 = ((const uint2*)&g_Xs_h[(size_t)s2 * NF])[lane];
        uint2 u3 = ((const uint2*)&g_Xs_h[(size_t)s3 * NF])[lane];
        // pair-add in fp16 (one rounding per pair), accumulate fp32
        half2 p01x = __hadd2(*(half2*)&u0.x, *(half2*)&u1.x);
        half2 p01y = __hadd2(*(half2*)&u0.y, *(half2*)&u1.y);
        half2 p23x = __hadd2(*(half2*)&u2.x, *(half2*)&u3.x);
        half2 p23y = __hadd2(*(half2*)&u2.y, *(half2*)&u3.y);
        float2 a = __half22float2(p01x), bb = __half22float2(p01y);
        float2 c = __half22float2(p23x), dd = __half22float2(p23y);
        acc0 += a.x + c.x; acc1 += a.y + c.y;
        acc2 += bb.x + dd.x; acc3 += bb.y + dd.y;
    }
#pragma unroll 1
    for (; e < e1; e++) {
        int s0 = g_col[e];
        uint2 u0 = ((const uint2*)&g_Xs_h[(size_t)s0 * NF])[lane];
        float2 a = __half22float2(*(half2*)&u0.x);
        float2 bb = __half22float2(*(half2*)&u0.y);
        acc0 += a.x; acc1 += a.y; acc2 += bb.x; acc3 += bb.y;
    }
    uint2 us = ((const uint2*)&g_Xs_h[(size_t)i * NF])[lane];
    float2 s01 = __half22float2(*(half2*)&us.x);
    float2 s23 = __half22float2(*(half2*)&us.y);
    float di = g_dinv[i];
    float v[4] = {di * (acc0 + s01.x), di * (acc1 + s01.y),
                  di * (acc2 + s23.x), di * (acc3 + s23.y)};
    __half h[4];
#pragma unroll
    for (int j = 0; j < 4; j++) h[j] = __float2half_rn(v[j]);
    *(uint2*)&g_AX_h[(size_t)i * NF + lane * 4] = *(uint2*)h;
}

// ---------------- 6. fused GEMM1 (fp16 1-term, M-tile 128, occ 2) ---------
#define SM_STRIDE 136
#define SMS (SM_STRIDE * 2)            // 272 B per row
#define TILE_B (128 * SMS)             // 34816 B
#define OFF_A    0
#define OFF_B0   TILE_B
#define OFF_B1   (2 * TILE_B)
#define OFF_CB1  (3 * TILE_B)
#define OFF_CW2X (OFF_CB1 + 2048)
#define OFF_CW2Y (OFF_CW2X + 2048)
#define OFF_RED  (OFF_CW2Y + 2048)
#define SMEM_BYTES (OFF_RED + 1024)

#define LDMX4(r0, r1, r2, r3, addr) \
    asm volatile("ldmatrix.sync.aligned.m8n8.x4.shared.b16 {%0,%1,%2,%3}, [%4];" \
        : "=r"(r0), "=r"(r1), "=r"(r2), "=r"(r3) : "r"(addr))

#define MMA16816(d, a, b) \
    asm volatile("mma.sync.aligned.m16n8k16.row.col.f32.f16.f16.f32 " \
        "{%0,%1,%2,%3}, {%4,%5,%6,%7}, {%8,%9}, {%0,%1,%2,%3};" \
        : "+f"((d)[0]), "+f"((d)[1]), "+f"((d)[2]), "+f"((d)[3]) \
        : "r"((a)[0]), "r"((a)[1]), "r"((a)[2]), "r"((a)[3]), "r"((b)[0]), "r"((b)[1]))

__device__ __forceinline__ void load_B_async(uint32_t sb, int nb, int buf, int tid) {
    int row = tid >> 1;
    int half = tid & 1;
    const char* src = (const char*)&g_W1T_h[(size_t)(nb * 128 + row) * NF + half * 64];
    uint32_t base = sb + (buf ? OFF_B1 : OFF_B0) + (uint32_t)row * SMS + half * 128;
#pragma unroll
    for (int i = 0; i < 8; i++) cp16(base + i * 16, src + i * 16, 16);
}

__global__ void __launch_bounds__(256, 2) k_gemm1_mma(const float* __restrict__ b1,
                                                      const float* __restrict__ W2) {
    extern __shared__ char smem[];
    const uint32_t sb = smem_u32(smem);
    const int tid  = threadIdx.x;
    const int lane = tid & 31;
    const int wid  = tid >> 5;
    const int wm   = wid & 3;
    const int wn   = wid >> 2;
    const int m0   = blockIdx.x * 128;

    {
        int row = tid >> 1;
        int half = tid & 1;
        int gr = m0 + row;
        int ok = (gr < N_NODES) ? 16 : 0;
        int grc = (gr < N_NODES) ? gr : 0;
        const char* srcA = (const char*)&g_AX_h[(size_t)grc * NF + half * 64];
        uint32_t dA = sb + OFF_A + (uint32_t)row * SMS + half * 128;
#pragma unroll
        for (int i = 0; i < 8; i++) cp16(dA + i * 16, srcA + i * 16, ok);
    }
    load_B_async(sb, 0, 0, tid);
    for (int i = tid; i < 512; i += 256) {
        ((float*)(smem + OFF_CB1))[i]  = b1[i];
        ((float*)(smem + OFF_CW2X))[i] = W2[i * 2 + 0];
        ((float*)(smem + OFF_CW2Y))[i] = W2[i * 2 + 1];
    }
    CP_COMMIT();
    CP_WAIT0();
    __syncthreads();

    const int a_row_in16 = lane & 15;
    const int a_k_half   = (lane >> 4) & 1;
    const int b_n_off    = (lane & 7) + ((lane & 16) ? 8 : 0);
    const int b_k_half   = (lane & 8) ? 1 : 0;
    const float* sB1  = (const float*)(smem + OFF_CB1);
    const float* sW2x = (const float*)(smem + OFF_CW2X);
    const float* sW2y = (const float*)(smem + OFF_CW2Y);
    const int g = lane >> 2;
    const int q = lane & 3;

    float p0[2][2], p1[2][2];
#pragma unroll
    for (int mt = 0; mt < 2; mt++)
#pragma unroll
        for (int rh = 0; rh < 2; rh++) { p0[mt][rh] = 0.f; p1[mt][rh] = 0.f; }

#pragma unroll 1
    for (int nb = 0; nb < 4; nb++) {
        if (nb < 3) { load_B_async(sb, nb + 1, (nb + 1) & 1, tid); CP_COMMIT(); }
        const uint32_t bbase = sb + ((nb & 1) ? OFF_B1 : OFF_B0);

        float d[2][8][4];
#pragma unroll
        for (int mt = 0; mt < 2; mt++)
#pragma unroll
            for (int nt = 0; nt < 8; nt++)
#pragma unroll
                for (int j = 0; j < 4; j++) d[mt][nt][j] = 0.0f;

#pragma unroll 1
        for (int k0 = 0; k0 < 128; k0 += 16) {
            uint32_t ah[2][4];
#pragma unroll
            for (int mt = 0; mt < 2; mt++) {
                int r = wm * 32 + mt * 16 + a_row_in16;
                uint32_t col = (uint32_t)(k0 + a_k_half * 8) * 2;
                LDMX4(ah[mt][0], ah[mt][1], ah[mt][2], ah[mt][3],
                      sb + OFF_A + (uint32_t)r * SMS + col);
            }
            uint32_t bh[8][2];
#pragma unroll
            for (int np = 0; np < 4; np++) {
                int nrow = wn * 64 + np * 16 + b_n_off;
                uint32_t col = (uint32_t)(k0 + b_k_half * 8) * 2;
                uint32_t r0, r1, r2, r3;
                LDMX4(r0, r1, r2, r3, bbase + (uint32_t)nrow * SMS + col);
                bh[np * 2][0] = r0; bh[np * 2][1] = r1;
                bh[np * 2 + 1][0] = r2; bh[np * 2 + 1][1] = r3;
            }
#pragma unroll
            for (int mt = 0; mt < 2; mt++)
#pragma unroll
                for (int nt = 0; nt < 8; nt++)
                    MMA16816(d[mt][nt], ah[mt], bh[nt]);
        }

#pragma unroll
        for (int mt = 0; mt < 2; mt++)
#pragma unroll
            for (int rh = 0; rh < 2; rh++)
#pragma unroll
                for (int nt = 0; nt < 8; nt++)
#pragma unroll
                    for (int j = 0; j < 2; j++) {
                        int col = nb * 128 + wn * 64 + nt * 8 + q * 2 + j;
                        float v = d[mt][nt][rh * 2 + j] + sB1[col];
                        v = fmaxf(v, 0.0f);
                        p0[mt][rh] += v * sW2x[col];
                        p1[mt][rh] += v * sW2y[col];
                    }

        if (nb < 3) { CP_WAIT0(); __syncthreads(); }
    }

    float pr0[2][2], pr1[2][2];
#pragma unroll
    for (int mt = 0; mt < 2; mt++)
#pragma unroll
        for (int rh = 0; rh < 2; rh++) {
            float a = p0[mt][rh], b = p1[mt][rh];
            a += __shfl_xor_sync(0xFFFFFFFFu, a, 1);
            b += __shfl_xor_sync(0xFFFFFFFFu, b, 1);
            a += __shfl_xor_sync(0xFFFFFFFFu, a, 2);
            b += __shfl_xor_sync(0xFFFFFFFFu, b, 2);
            pr0[mt][rh] = a; pr1[mt][rh] = b;
        }
    float2* red = (float2*)(smem + OFF_RED);
    __syncthreads();
    if (wn == 1 && q == 0) {
#pragma unroll
        for (int mt = 0; mt < 2; mt++)
#pragma unroll
            for (int rh = 0; rh < 2; rh++) {
                int lr = wm * 32 + mt * 16 + rh * 8 + g;
                red[lr] = make_float2(pr0[mt][rh], pr1[mt][rh]);
            }
    }
    __syncthreads();
    if (wn == 0 && q == 0) {
#pragma unroll
        for (int mt = 0; mt < 2; mt++)
#pragma unroll
            for (int rh = 0; rh < 2; rh++) {
                int lr = wm * 32 + mt * 16 + rh * 8 + g;
                int row = m0 + lr;
                if (row < N_NODES) {
                    float2 o = red[lr];
                    float di = g_dinv[row];
                    g_HW2[row] = make_float2(di * (pr0[mt][rh] + o.x),
                                             di * (pr1[mt][rh] + o.y));
                }
            }
    }
}

// ---------------- 7. aggregate layer2 (warp/node) + softmax ----------------
__global__ void __launch_bounds__(256) k_agg2(const float* __restrict__ b2,
                                              float* __restrict__ out) {
    int gw = (blockIdx.x * blockDim.x + threadIdx.x) >> 5;
    int lane = threadIdx.x & 31;
    if (gw >= N_NODES) return;
    int i = gw;
    int e0 = g_rowptr[i], e1 = g_rowptr[i + 1];
    float a0 = 0.f, a1 = 0.f;
    for (int e = e0 + lane; e < e1; e += 32) {
        float2 m = g_HW2[g_col[e]];
        a0 += m.x;
        a1 += m.y;
    }
#pragma unroll
    for (int off = 16; off > 0; off >>= 1) {
        a0 += __shfl_xor_sync(0xFFFFFFFFu, a0, off);
        a1 += __shfl_xor_sync(0xFFFFFFFFu, a1, off);
    }
    if (lane == 0) {
        float di = g_dinv[i];
        float2 self = g_HW2[i];
        float l0 = di * (a0 + self.x) + b2[0];
        float l1 = di * (a1 + self.y) + b2[1];
        float mx = fmaxf(l0, l1);
        float e0f = __expf(l0 - mx);
        float e1f = __expf(l1 - mx);
        float inv = 1.0f / (e0f + e1f);
        out[(size_t)i * 2 + 0] = e0f * inv;
        out[(size_t)i * 2 + 1] = e1f * inv;
    }
}

// ---------------- launch ----------------
extern "C" void kernel_launch(void* const* d_in, const int* in_sizes, int n_in,
                              void* d_out, int out_size) {
    const float* X  = (const float*)d_in[0];
    const void*  EI = d_in[1];
    const float* W1 = (const float*)d_in[2];
    const float* b1 = (const float*)d_in[3];
    const float* W2 = (const float*)d_in[4];
    const float* b2 = (const float*)d_in[5];
    float* out = (float*)d_out;
    (void)in_sizes; (void)n_in; (void)out_size;

    cudaFuncSetAttribute(k_gemm1_mma, cudaFuncAttributeMaxDynamicSharedMemorySize, SMEM_BYTES);

    k_count_w1t<<<NE2_BLOCKS + W1T_BLOCKS, 256>>>(EI, W1);
    k_bsum<<<NBLK, 256>>>();
    k_bscan<<<NBLK, 256>>>();
    k_scatter_xs<<<NE2_BLOCKS + XS_BLOCKS + NBLK, 256>>>(EI, X);
    k_agg1<<<(N_NODES * 32 + 255) / 256, 256>>>();
    k_gemm1_mma<<<(N_NODES + 127) / 128, 256, SMEM_BYTES>>>(b1, W2);
    k_agg2<<<(N_NODES * 32 + 255) / 256, 256>>>(b2, out);
}